// round 10
// baseline (speedup 1.0000x reference)
#include <cuda_runtime.h>
#include <math.h>
#include <stdint.h>

// Problem constants
#define BB   2
#define SS   2048
#define EE   2048
#define HH   32
#define DKQ  32
#define DVV  32
#define RK   1024
#define MM   (BB*SS)   // 4096

// Scratch (no cudaMalloc allowed)
__device__ float g_q[MM * RK];
__device__ float g_k[MM * RK];
__device__ float g_v[MM * RK];
__device__ float g_att[MM * RK];

// ---------------------------------------------------------------------------
// tf32 helpers
// ---------------------------------------------------------------------------
__device__ __forceinline__ uint32_t f2tf32(float x) {
    uint32_t r;
    asm("cvt.rna.tf32.f32 %0, %1;" : "=r"(r) : "f"(x));
    return r;
}

__device__ __forceinline__ void mma_tf32(float* c, const uint32_t* a, const uint32_t* b) {
    asm volatile(
        "mma.sync.aligned.m16n8k8.row.col.f32.tf32.tf32.f32 "
        "{%0,%1,%2,%3}, {%4,%5,%6,%7}, {%8,%9}, {%0,%1,%2,%3};"
        : "+f"(c[0]), "+f"(c[1]), "+f"(c[2]), "+f"(c[3])
        : "r"(a[0]), "r"(a[1]), "r"(a[2]), "r"(a[3]),
          "r"(b[0]), "r"(b[1]));
}

// ---------------------------------------------------------------------------
// tf32 tensor-core GEMM body:
//   C[m][n] = alpha * ( sum_k A[m][k]*W[n][k] + bias[n] )   (C = A @ W^T)
// Block tile 128x128, K-step 16. 256 threads = 8 warps in 2(M) x 4(N) grid,
// warp tile 64x32 = 4x4 grid of m16n8k8 MMAs.
// SMEM stride 20 floats: fragment loads hit all 32 banks (g*20+lq mod 32).
// Requires: Md % 128 == 0, Nd % 128 == 0, Kd % 16 == 0 (true for all calls).
// ---------------------------------------------------------------------------
__device__ __forceinline__ void gemm_body(
    const float* __restrict__ A, const float* __restrict__ W,
    const float* __restrict__ bias, float* __restrict__ C,
    int Nd, int Kd, float alpha, int bm, int bn)
{
    __shared__ uint32_t As[128][20];
    __shared__ uint32_t Bs[128][20];

    const int tid  = threadIdx.x;
    const int lane = tid & 31;
    const int warp = tid >> 5;
    const int g    = lane >> 2;      // 0..7
    const int lq   = lane & 3;       // 0..3
    const int wm   = (warp & 1) << 6;   // 0 or 64
    const int wn   = (warp >> 1) << 5;  // 0,32,64,96

    const int lrow = tid >> 2;          // 0..63
    const int lkg  = (tid & 3) << 2;    // 0,4,8,12

    const float* Ag0 = A + (size_t)(bm + lrow)      * Kd + lkg;
    const float* Ag1 = A + (size_t)(bm + lrow + 64) * Kd + lkg;
    const float* Wg0 = W + (size_t)(bn + lrow)      * Kd + lkg;
    const float* Wg1 = W + (size_t)(bn + lrow + 64) * Kd + lkg;

    float acc[4][4][4];
    #pragma unroll
    for (int i = 0; i < 4; i++)
        #pragma unroll
        for (int j = 0; j < 4; j++)
            #pragma unroll
            for (int e = 0; e < 4; e++) acc[i][j][e] = 0.f;

    // Prefetch first K-slab into registers
    float4 fa0 = *(const float4*)Ag0;
    float4 fa1 = *(const float4*)Ag1;
    float4 fb0 = *(const float4*)Wg0;
    float4 fb1 = *(const float4*)Wg1;

    for (int k0 = 0; k0 < Kd; k0 += 16) {
        // reg -> smem (convert to tf32 once per element here)
        As[lrow][lkg + 0] = f2tf32(fa0.x); As[lrow][lkg + 1] = f2tf32(fa0.y);
        As[lrow][lkg + 2] = f2tf32(fa0.z); As[lrow][lkg + 3] = f2tf32(fa0.w);
        As[lrow + 64][lkg + 0] = f2tf32(fa1.x); As[lrow + 64][lkg + 1] = f2tf32(fa1.y);
        As[lrow + 64][lkg + 2] = f2tf32(fa1.z); As[lrow + 64][lkg + 3] = f2tf32(fa1.w);
        Bs[lrow][lkg + 0] = f2tf32(fb0.x); Bs[lrow][lkg + 1] = f2tf32(fb0.y);
        Bs[lrow][lkg + 2] = f2tf32(fb0.z); Bs[lrow][lkg + 3] = f2tf32(fb0.w);
        Bs[lrow + 64][lkg + 0] = f2tf32(fb1.x); Bs[lrow + 64][lkg + 1] = f2tf32(fb1.y);
        Bs[lrow + 64][lkg + 2] = f2tf32(fb1.z); Bs[lrow + 64][lkg + 3] = f2tf32(fb1.w);
        __syncthreads();

        // prefetch next slab while MMAs run
        if (k0 + 16 < Kd) {
            Ag0 += 16; Ag1 += 16; Wg0 += 16; Wg1 += 16;
            fa0 = *(const float4*)Ag0;
            fa1 = *(const float4*)Ag1;
            fb0 = *(const float4*)Wg0;
            fb1 = *(const float4*)Wg1;
        }

        #pragma unroll
        for (int ks = 0; ks < 16; ks += 8) {
            uint32_t af[4][4], bf[4][2];
            #pragma unroll
            for (int i = 0; i < 4; i++) {
                const int r = wm + i * 16 + g;
                af[i][0] = As[r][ks + lq];
                af[i][1] = As[r + 8][ks + lq];
                af[i][2] = As[r][ks + lq + 4];
                af[i][3] = As[r + 8][ks + lq + 4];
            }
            #pragma unroll
            for (int j = 0; j < 4; j++) {
                const int n = wn + j * 8 + g;
                bf[j][0] = Bs[n][ks + lq];
                bf[j][1] = Bs[n][ks + lq + 4];
            }
            #pragma unroll
            for (int i = 0; i < 4; i++)
                #pragma unroll
                for (int j = 0; j < 4; j++)
                    mma_tf32(acc[i][j], af[i], bf[j]);
        }
        __syncthreads();
    }

    // Epilogue: C fragment layout m16n8: (g, 2*lq), (g, 2*lq+1), (g+8, ...)
    #pragma unroll
    for (int i = 0; i < 4; i++) {
        const int row = bm + wm + i * 16 + g;
        #pragma unroll
        for (int j = 0; j < 4; j++) {
            const int col = bn + wn + j * 8 + (lq << 1);
            const float b0 = bias[col], b1 = bias[col + 1];
            float* c0 = C + (size_t)row * Nd + col;
            float* c1 = C + (size_t)(row + 8) * Nd + col;
            c0[0] = alpha * (acc[i][j][0] + b0);
            c0[1] = alpha * (acc[i][j][1] + b1);
            c1[0] = alpha * (acc[i][j][2] + b0);
            c1[1] = alpha * (acc[i][j][3] + b1);
        }
    }
}

// Fused q/k/v projection: blockIdx.z selects the weight/bias/output triple.
__global__ __launch_bounds__(256) void gemm_qkv(
    const float* __restrict__ hidden,
    const float* __restrict__ Wq, const float* __restrict__ bq,
    const float* __restrict__ Wk, const float* __restrict__ bk,
    const float* __restrict__ Wv, const float* __restrict__ bv,
    float* __restrict__ q, float* __restrict__ k, float* __restrict__ v,
    float scaling)
{
    const float* W; const float* bias; float* C; float alpha;
    if (blockIdx.z == 0)      { W = Wq; bias = bq; C = q; alpha = scaling; }
    else if (blockIdx.z == 1) { W = Wk; bias = bk; C = k; alpha = 1.f; }
    else                      { W = Wv; bias = bv; C = v; alpha = 1.f; }
    gemm_body(hidden, W, bias, C, RK, EE, alpha, blockIdx.y * 128, blockIdx.x * 128);
}

__global__ __launch_bounds__(256) void gemm_o(
    const float* __restrict__ att,
    const float* __restrict__ Wo, const float* __restrict__ bo,
    float* __restrict__ out)
{
    gemm_body(att, Wo, bo, out, EE, RK, 1.f, blockIdx.y * 128, blockIdx.x * 128);
}

// ---------------------------------------------------------------------------
// Flash attention (unchanged from R5). One block = one (b, h, q-tile of 64).
// ---------------------------------------------------------------------------
__global__ __launch_bounds__(256) void flash_attn(const float* __restrict__ mask)
{
    __shared__ float Qs[64][33];
    __shared__ float Ks[64][33];
    __shared__ float Vs[64][32];
    __shared__ float Ps[64][65];

    const int b  = blockIdx.z;
    const int h  = blockIdx.y;
    const int qi = blockIdx.x;
    const int q0 = qi * 64;

    const int tid = threadIdx.x;
    const int row = tid >> 2;
    const int cg  = tid & 3;
    const int cbase = cg * 16;
    const int dvb   = cg * 8;

    for (int e = tid; e < 64 * 32; e += 256) {
        int r = e >> 5, d = e & 31;
        Qs[r][d] = g_q[((size_t)(b * SS + q0 + r)) * RK + h * DKQ + d];
    }

    float m_i = -INFINITY, l_i = 0.f;
    float o[8];
    #pragma unroll
    for (int j = 0; j < 8; j++) o[j] = 0.f;

    const int ntiles = qi + 1;  // causal
    for (int t = 0; t < ntiles; t++) {
        const int k0 = t * 64;
        __syncthreads();
        for (int e = tid; e < 64 * 32; e += 256) {
            int r = e >> 5, d = e & 31;
            size_t gi = ((size_t)(b * SS + k0 + r)) * RK + h * DKQ + d;
            Ks[r][d] = g_k[gi];
            Vs[r][d] = g_v[gi];
        }
        __syncthreads();

        float s[16];
        #pragma unroll
        for (int j = 0; j < 16; j++) s[j] = 0.f;
        #pragma unroll
        for (int d = 0; d < 32; d++) {
            float qd = Qs[row][d];
            #pragma unroll
            for (int j = 0; j < 16; j++)
                s[j] += qd * Ks[cbase + j][d];
        }

        const float* mrow = mask + ((size_t)b * SS + (q0 + row)) * SS + k0 + cbase;
        float tmax = -INFINITY;
        #pragma unroll
        for (int j = 0; j < 16; j++) {
            s[j] = fmaxf(s[j] + mrow[j], -3.402823466e38f);
            tmax = fmaxf(tmax, s[j]);
        }
        tmax = fmaxf(tmax, __shfl_xor_sync(0xffffffffu, tmax, 1));
        tmax = fmaxf(tmax, __shfl_xor_sync(0xffffffffu, tmax, 2));

        const float m_new = fmaxf(m_i, tmax);
        const float scale = __expf(m_i - m_new);

        float lsum = 0.f;
        #pragma unroll
        for (int j = 0; j < 16; j++) {
            float p = __expf(s[j] - m_new);
            Ps[row][cbase + j] = p;
            lsum += p;
        }
        lsum += __shfl_xor_sync(0xffffffffu, lsum, 1);
        lsum += __shfl_xor_sync(0xffffffffu, lsum, 2);

        l_i = l_i * scale + lsum;
        m_i = m_new;

        #pragma unroll
        for (int j = 0; j < 8; j++) o[j] *= scale;

        __syncwarp();
        for (int k = 0; k < 64; k++) {
            float p = Ps[row][k];
            #pragma unroll
            for (int j = 0; j < 8; j++)
                o[j] += p * Vs[k][dvb + j];
        }
        __syncwarp();
    }

    const float inv = 1.f / l_i;
    size_t ob = ((size_t)(b * SS + q0 + row)) * RK + h * DVV + dvb;
    #pragma unroll
    for (int j = 0; j < 8; j++)
        g_att[ob + j] = o[j] * inv;
}

// ---------------------------------------------------------------------------
extern "C" void kernel_launch(void* const* d_in, const int* in_sizes, int n_in,
                              void* d_out, int out_size)
{
    const float* hidden = (const float*)d_in[0];
    const float* mask   = (const float*)d_in[1];
    const float* Wq     = (const float*)d_in[2];
    const float* bq     = (const float*)d_in[3];
    const float* Wk     = (const float*)d_in[4];
    const float* bk     = (const float*)d_in[5];
    const float* Wv     = (const float*)d_in[6];
    const float* bv     = (const float*)d_in[7];
    const float* Wo     = (const float*)d_in[8];
    const float* bo     = (const float*)d_in[9];
    float* out = (float*)d_out;

    float* q = nullptr; float* k = nullptr; float* v = nullptr; float* att = nullptr;
    cudaGetSymbolAddress((void**)&q,   g_q);
    cudaGetSymbolAddress((void**)&k,   g_k);
    cudaGetSymbolAddress((void**)&v,   g_v);
    cudaGetSymbolAddress((void**)&att, g_att);

    const float scaling = 0.125f;  // 64^-0.5 (original head dim)

    // Fused projections: (4096 x 2048) @ (1024 x 2048)^T -> 3x (4096 x 1024)
    {
        dim3 grid(RK / 128, MM / 128, 3);
        gemm_qkv<<<grid, 256>>>(hidden, Wq, bq, Wk, bk, Wv, bv, q, k, v, scaling);
    }

    // Attention
    {
        dim3 grid(SS / 64, HH, BB);
        flash_attn<<<grid, 256>>>(mask);
    }

    // Output projection: (4096 x 1024) @ (2048 x 1024)^T -> (4096 x 2048)
    {
        dim3 grid(EE / 128, MM / 128);
        gemm_o<<<grid, 256>>>(att, Wo, bo, out);
    }
}

// round 14
// speedup vs baseline: 2.8064x; 2.8064x over previous
#include <cuda_runtime.h>
#include <math.h>
#include <stdint.h>

// Problem constants
#define BB   2
#define SS   2048
#define EE   2048
#define HH   32
#define DKQ  32
#define DVV  32
#define RK   1024
#define MM   (BB*SS)   // 4096

#define NEG_BIG (-1e30f)

// Scratch (no cudaMalloc allowed)
__device__ float g_q[MM * RK];
__device__ float g_k[MM * RK];
__device__ float g_v[MM * RK];
__device__ float g_att[MM * RK];

// ---------------------------------------------------------------------------
// tf32 helpers
// ---------------------------------------------------------------------------
__device__ __forceinline__ uint32_t f2tf32(float x) {
    uint32_t r;
    asm("cvt.rna.tf32.f32 %0, %1;" : "=r"(r) : "f"(x));
    return r;
}

__device__ __forceinline__ void mma_tf32(float* c, const uint32_t* a, const uint32_t* b) {
    asm volatile(
        "mma.sync.aligned.m16n8k8.row.col.f32.tf32.tf32.f32 "
        "{%0,%1,%2,%3}, {%4,%5,%6,%7}, {%8,%9}, {%0,%1,%2,%3};"
        : "+f"(c[0]), "+f"(c[1]), "+f"(c[2]), "+f"(c[3])
        : "r"(a[0]), "r"(a[1]), "r"(a[2]), "r"(a[3]),
          "r"(b[0]), "r"(b[1]));
}

// ---------------------------------------------------------------------------
// tf32 tensor-core GEMM body (unchanged from R10):
//   C[m][n] = alpha * ( sum_k A[m][k]*W[n][k] + bias[n] )   (C = A @ W^T)
// ---------------------------------------------------------------------------
__device__ __forceinline__ void gemm_body(
    const float* __restrict__ A, const float* __restrict__ W,
    const float* __restrict__ bias, float* __restrict__ C,
    int Nd, int Kd, float alpha, int bm, int bn)
{
    __shared__ uint32_t As[128][20];
    __shared__ uint32_t Bs[128][20];

    const int tid  = threadIdx.x;
    const int lane = tid & 31;
    const int warp = tid >> 5;
    const int g    = lane >> 2;      // 0..7
    const int lq   = lane & 3;       // 0..3
    const int wm   = (warp & 1) << 6;   // 0 or 64
    const int wn   = (warp >> 1) << 5;  // 0,32,64,96

    const int lrow = tid >> 2;          // 0..63
    const int lkg  = (tid & 3) << 2;    // 0,4,8,12

    const float* Ag0 = A + (size_t)(bm + lrow)      * Kd + lkg;
    const float* Ag1 = A + (size_t)(bm + lrow + 64) * Kd + lkg;
    const float* Wg0 = W + (size_t)(bn + lrow)      * Kd + lkg;
    const float* Wg1 = W + (size_t)(bn + lrow + 64) * Kd + lkg;

    float acc[4][4][4];
    #pragma unroll
    for (int i = 0; i < 4; i++)
        #pragma unroll
        for (int j = 0; j < 4; j++)
            #pragma unroll
            for (int e = 0; e < 4; e++) acc[i][j][e] = 0.f;

    float4 fa0 = *(const float4*)Ag0;
    float4 fa1 = *(const float4*)Ag1;
    float4 fb0 = *(const float4*)Wg0;
    float4 fb1 = *(const float4*)Wg1;

    for (int k0 = 0; k0 < Kd; k0 += 16) {
        As[lrow][lkg + 0] = f2tf32(fa0.x); As[lrow][lkg + 1] = f2tf32(fa0.y);
        As[lrow][lkg + 2] = f2tf32(fa0.z); As[lrow][lkg + 3] = f2tf32(fa0.w);
        As[lrow + 64][lkg + 0] = f2tf32(fa1.x); As[lrow + 64][lkg + 1] = f2tf32(fa1.y);
        As[lrow + 64][lkg + 2] = f2tf32(fa1.z); As[lrow + 64][lkg + 3] = f2tf32(fa1.w);
        Bs[lrow][lkg + 0] = f2tf32(fb0.x); Bs[lrow][lkg + 1] = f2tf32(fb0.y);
        Bs[lrow][lkg + 2] = f2tf32(fb0.z); Bs[lrow][lkg + 3] = f2tf32(fb0.w);
        Bs[lrow + 64][lkg + 0] = f2tf32(fb1.x); Bs[lrow + 64][lkg + 1] = f2tf32(fb1.y);
        Bs[lrow + 64][lkg + 2] = f2tf32(fb1.z); Bs[lrow + 64][lkg + 3] = f2tf32(fb1.w);
        __syncthreads();

        if (k0 + 16 < Kd) {
            Ag0 += 16; Ag1 += 16; Wg0 += 16; Wg1 += 16;
            fa0 = *(const float4*)Ag0;
            fa1 = *(const float4*)Ag1;
            fb0 = *(const float4*)Wg0;
            fb1 = *(const float4*)Wg1;
        }

        #pragma unroll
        for (int ks = 0; ks < 16; ks += 8) {
            uint32_t af[4][4], bf[4][2];
            #pragma unroll
            for (int i = 0; i < 4; i++) {
                const int r = wm + i * 16 + g;
                af[i][0] = As[r][ks + lq];
                af[i][1] = As[r + 8][ks + lq];
                af[i][2] = As[r][ks + lq + 4];
                af[i][3] = As[r + 8][ks + lq + 4];
            }
            #pragma unroll
            for (int j = 0; j < 4; j++) {
                const int n = wn + j * 8 + g;
                bf[j][0] = Bs[n][ks + lq];
                bf[j][1] = Bs[n][ks + lq + 4];
            }
            #pragma unroll
            for (int i = 0; i < 4; i++)
                #pragma unroll
                for (int j = 0; j < 4; j++)
                    mma_tf32(acc[i][j], af[i], bf[j]);
        }
        __syncthreads();
    }

    #pragma unroll
    for (int i = 0; i < 4; i++) {
        const int row = bm + wm + i * 16 + g;
        #pragma unroll
        for (int j = 0; j < 4; j++) {
            const int col = bn + wn + j * 8 + (lq << 1);
            const float b0 = bias[col], b1 = bias[col + 1];
            float* c0 = C + (size_t)row * Nd + col;
            float* c1 = C + (size_t)(row + 8) * Nd + col;
            c0[0] = alpha * (acc[i][j][0] + b0);
            c0[1] = alpha * (acc[i][j][1] + b1);
            c1[0] = alpha * (acc[i][j][2] + b0);
            c1[1] = alpha * (acc[i][j][3] + b1);
        }
    }
}

__global__ __launch_bounds__(256) void gemm_qkv(
    const float* __restrict__ hidden,
    const float* __restrict__ Wq, const float* __restrict__ bq,
    const float* __restrict__ Wk, const float* __restrict__ bk,
    const float* __restrict__ Wv, const float* __restrict__ bv,
    float* __restrict__ q, float* __restrict__ k, float* __restrict__ v,
    float scaling)
{
    const float* W; const float* bias; float* C; float alpha;
    if (blockIdx.z == 0)      { W = Wq; bias = bq; C = q; alpha = scaling; }
    else if (blockIdx.z == 1) { W = Wk; bias = bk; C = k; alpha = 1.f; }
    else                      { W = Wv; bias = bv; C = v; alpha = 1.f; }
    gemm_body(hidden, W, bias, C, RK, EE, alpha, blockIdx.y * 128, blockIdx.x * 128);
}

__global__ __launch_bounds__(256) void gemm_o(
    const float* __restrict__ att,
    const float* __restrict__ Wo, const float* __restrict__ bo,
    float* __restrict__ out)
{
    gemm_body(att, Wo, bo, out, EE, RK, 1.f, blockIdx.y * 128, blockIdx.x * 128);
}

// ---------------------------------------------------------------------------
// Tensor-core flash attention (tf32 mma, FA2-style register softmax).
// One block = (b, h, 64-row q-tile). 128 threads = 4 warps; warp w owns
// q-rows [wm, wm+16). Causal mask applied analytically with a finite
// large-negative value (no inf arithmetic anywhere).
//
// R13 fix: the row-sum l is now quad-reduced (shfl xor 1,2) like the row max.
// Without that, lanes whose 16 columns are all causally masked carried l=0
// and produced 0 * (1/0) = NaN in the epilogue (q-row 0 always hit this).
// ---------------------------------------------------------------------------
__global__ __launch_bounds__(128) void flash_attn_mma()
{
    __shared__ uint32_t Qs[64][36];
    __shared__ uint32_t Ks[64][36];
    __shared__ uint32_t Vs[64][36];
    __shared__ uint32_t Ps[64][68];

    const int b  = blockIdx.z;
    const int h  = blockIdx.y;
    const int qi = blockIdx.x;
    const int q0 = qi * 64;

    const int tid  = threadIdx.x;
    const int lane = tid & 31;
    const int warp = tid >> 5;
    const int g    = lane >> 2;   // 0..7
    const int lq   = lane & 3;    // 0..3
    const int wm   = warp << 4;   // 0,16,32,48

    // Load Q tile (64x32), convert to tf32 once.
    for (int i = tid; i < 512; i += 128) {
        const int r = i >> 3, c = (i & 7) << 2;
        float4 f = *(const float4*)&g_q[((size_t)(b * SS + q0 + r)) * RK + h * DKQ + c];
        *(uint4*)&Qs[r][c] = make_uint4(f2tf32(f.x), f2tf32(f.y), f2tf32(f.z), f2tf32(f.w));
    }

    const int r0 = q0 + wm + g;      // first of this thread's two q-rows
    float m0 = NEG_BIG, m1 = NEG_BIG;
    float l0 = 0.f, l1 = 0.f;
    float o[4][4];
    #pragma unroll
    for (int j = 0; j < 4; j++)
        #pragma unroll
        for (int e = 0; e < 4; e++) o[j][e] = 0.f;

    for (int t = 0; t <= qi; t++) {
        const int k0 = t * 64;
        __syncthreads();   // prior tile's K/V consumers done (covers Q on t=0)
        for (int i = tid; i < 512; i += 128) {
            const int r = i >> 3, c = (i & 7) << 2;
            const size_t gi = ((size_t)(b * SS + k0 + r)) * RK + h * DKQ + c;
            float4 fk = *(const float4*)&g_k[gi];
            float4 fv = *(const float4*)&g_v[gi];
            *(uint4*)&Ks[r][c] = make_uint4(f2tf32(fk.x), f2tf32(fk.y), f2tf32(fk.z), f2tf32(fk.w));
            *(uint4*)&Vs[r][c] = make_uint4(f2tf32(fv.x), f2tf32(fv.y), f2tf32(fv.z), f2tf32(fv.w));
        }
        __syncthreads();

        // ---- S = Q K^T : m16 x n64 x k32 ----
        float s[8][4];
        #pragma unroll
        for (int j = 0; j < 8; j++)
            #pragma unroll
            for (int e = 0; e < 4; e++) s[j][e] = 0.f;

        #pragma unroll
        for (int ks = 0; ks < 32; ks += 8) {
            uint32_t af[4];
            af[0] = Qs[wm + g][ks + lq];
            af[1] = Qs[wm + 8 + g][ks + lq];
            af[2] = Qs[wm + g][ks + lq + 4];
            af[3] = Qs[wm + 8 + g][ks + lq + 4];
            #pragma unroll
            for (int j = 0; j < 8; j++) {
                uint32_t bf[2];
                bf[0] = Ks[j * 8 + g][ks + lq];
                bf[1] = Ks[j * 8 + g][ks + lq + 4];
                mma_tf32(s[j], af, bf);
            }
        }

        // ---- causal mask (diagonal tile only); finite sentinel ----
        if (t == qi) {
            #pragma unroll
            for (int j = 0; j < 8; j++) {
                const int col = k0 + j * 8 + (lq << 1);
                if (col     > r0)     s[j][0] = NEG_BIG;
                if (col + 1 > r0)     s[j][1] = NEG_BIG;
                if (col     > r0 + 8) s[j][2] = NEG_BIG;
                if (col + 1 > r0 + 8) s[j][3] = NEG_BIG;
            }
        }

        // ---- online softmax (rows r0 and r0+8) ----
        float t0 = NEG_BIG, t1 = NEG_BIG;
        #pragma unroll
        for (int j = 0; j < 8; j++) {
            t0 = fmaxf(t0, fmaxf(s[j][0], s[j][1]));
            t1 = fmaxf(t1, fmaxf(s[j][2], s[j][3]));
        }
        t0 = fmaxf(t0, __shfl_xor_sync(0xffffffffu, t0, 1));
        t0 = fmaxf(t0, __shfl_xor_sync(0xffffffffu, t0, 2));
        t1 = fmaxf(t1, __shfl_xor_sync(0xffffffffu, t1, 1));
        t1 = fmaxf(t1, __shfl_xor_sync(0xffffffffu, t1, 2));

        const float mn0 = fmaxf(m0, t0);
        const float mn1 = fmaxf(m1, t1);
        const float sc0 = __expf(m0 - mn0);
        const float sc1 = __expf(m1 - mn1);

        float ls0 = 0.f, ls1 = 0.f;
        #pragma unroll
        for (int j = 0; j < 8; j++) {
            const float p00 = __expf(s[j][0] - mn0);
            const float p01 = __expf(s[j][1] - mn0);
            const float p10 = __expf(s[j][2] - mn1);
            const float p11 = __expf(s[j][3] - mn1);
            ls0 += p00 + p01;
            ls1 += p10 + p11;
            const int pc = j * 8 + (lq << 1);
            *(uint2*)&Ps[wm + g][pc]     = make_uint2(f2tf32(p00), f2tf32(p01));
            *(uint2*)&Ps[wm + 8 + g][pc] = make_uint2(f2tf32(p10), f2tf32(p11));
        }
        // R13 FIX: reduce the row sums across the quad (was missing -> l=0
        // on fully-masked lanes -> 1/l = inf -> 0*inf = NaN).
        ls0 += __shfl_xor_sync(0xffffffffu, ls0, 1);
        ls0 += __shfl_xor_sync(0xffffffffu, ls0, 2);
        ls1 += __shfl_xor_sync(0xffffffffu, ls1, 1);
        ls1 += __shfl_xor_sync(0xffffffffu, ls1, 2);

        l0 = l0 * sc0 + ls0;
        l1 = l1 * sc1 + ls1;
        m0 = mn0;
        m1 = mn1;

        #pragma unroll
        for (int j = 0; j < 4; j++) {
            o[j][0] *= sc0; o[j][1] *= sc0;
            o[j][2] *= sc1; o[j][3] *= sc1;
        }

        __syncwarp();   // Ps is warp-private: warp-level fence suffices

        // ---- O += P V : m16 x n32 x k64 ----
        #pragma unroll
        for (int ks = 0; ks < 64; ks += 8) {
            uint32_t af[4];
            af[0] = Ps[wm + g][ks + lq];
            af[1] = Ps[wm + 8 + g][ks + lq];
            af[2] = Ps[wm + g][ks + lq + 4];
            af[3] = Ps[wm + 8 + g][ks + lq + 4];
            #pragma unroll
            for (int j = 0; j < 4; j++) {
                uint32_t bf[2];
                bf[0] = Vs[ks + lq][j * 8 + g];
                bf[1] = Vs[ks + lq + 4][j * 8 + g];
                mma_tf32(o[j], af, bf);
            }
        }
    }

    // ---- epilogue ----
    const float inv0 = 1.f / l0;
    const float inv1 = 1.f / l1;
    const size_t base0 = ((size_t)(b * SS + r0))     * RK + h * DVV;
    const size_t base1 = ((size_t)(b * SS + r0 + 8)) * RK + h * DVV;
    #pragma unroll
    for (int j = 0; j < 4; j++) {
        const int col = j * 8 + (lq << 1);
        g_att[base0 + col]     = o[j][0] * inv0;
        g_att[base0 + col + 1] = o[j][1] * inv0;
        g_att[base1 + col]     = o[j][2] * inv1;
        g_att[base1 + col + 1] = o[j][3] * inv1;
    }
}

// ---------------------------------------------------------------------------
extern "C" void kernel_launch(void* const* d_in, const int* in_sizes, int n_in,
                              void* d_out, int out_size)
{
    const float* hidden = (const float*)d_in[0];
    const float* Wq     = (const float*)d_in[2];
    const float* bq     = (const float*)d_in[3];
    const float* Wk     = (const float*)d_in[4];
    const float* bk     = (const float*)d_in[5];
    const float* Wv     = (const float*)d_in[6];
    const float* bv     = (const float*)d_in[7];
    const float* Wo     = (const float*)d_in[8];
    const float* bo     = (const float*)d_in[9];
    float* out = (float*)d_out;

    float* q = nullptr; float* k = nullptr; float* v = nullptr; float* att = nullptr;
    cudaGetSymbolAddress((void**)&q,   g_q);
    cudaGetSymbolAddress((void**)&k,   g_k);
    cudaGetSymbolAddress((void**)&v,   g_v);
    cudaGetSymbolAddress((void**)&att, g_att);

    const float scaling = 0.125f;  // 64^-0.5 (original head dim)

    // Fused projections: (4096 x 2048) @ (1024 x 2048)^T -> 3x (4096 x 1024)
    {
        dim3 grid(RK / 128, MM / 128, 3);
        gemm_qkv<<<grid, 256>>>(hidden, Wq, bq, Wk, bk, Wv, bv, q, k, v, scaling);
    }

    // Attention (tensor-core flash; analytic causal mask)
    {
        dim3 grid(SS / 64, HH, BB);
        flash_attn_mma<<<grid, 128>>>();
    }

    // Output projection: (4096 x 1024) @ (2048 x 1024)^T -> (4096 x 2048)
    {
        dim3 grid(EE / 128, MM / 128);
        gemm_o<<<grid, 256>>>(att, Wo, bo, out);
    }
}

// round 15
// speedup vs baseline: 3.6458x; 1.2991x over previous
#include <cuda_runtime.h>
#include <math.h>
#include <stdint.h>

// Problem constants
#define BB   2
#define SS   2048
#define EE   2048
#define HH   32
#define DKQ  32
#define DVV  32
#define RK   1024
#define MM   (BB*SS)   // 4096

#define NEG_BIG (-1e30f)

// Scratch (no cudaMalloc allowed)
__device__ float g_q[MM * RK];
__device__ float g_k[MM * RK];
__device__ float g_v[MM * RK];
__device__ float g_att[MM * RK];

// ---------------------------------------------------------------------------
// tf32 / mma / ldmatrix / cp.async helpers
// ---------------------------------------------------------------------------
__device__ __forceinline__ uint32_t f2tf32(float x) {
    uint32_t r;
    asm("cvt.rna.tf32.f32 %0, %1;" : "=r"(r) : "f"(x));
    return r;
}

__device__ __forceinline__ void mma_tf32(float* c, const uint32_t* a, const uint32_t* b) {
    asm volatile(
        "mma.sync.aligned.m16n8k8.row.col.f32.tf32.tf32.f32 "
        "{%0,%1,%2,%3}, {%4,%5,%6,%7}, {%8,%9}, {%0,%1,%2,%3};"
        : "+f"(c[0]), "+f"(c[1]), "+f"(c[2]), "+f"(c[3])
        : "r"(a[0]), "r"(a[1]), "r"(a[2]), "r"(a[3]),
          "r"(b[0]), "r"(b[1]));
}

__device__ __forceinline__ void ldsm_x4(uint32_t* r, uint32_t saddr) {
    asm volatile(
        "ldmatrix.sync.aligned.m8n8.x4.shared.b16 {%0,%1,%2,%3}, [%4];"
        : "=r"(r[0]), "=r"(r[1]), "=r"(r[2]), "=r"(r[3]) : "r"(saddr));
}

__device__ __forceinline__ void cp_async16(uint32_t dst_saddr, const void* src) {
    asm volatile("cp.async.cg.shared.global [%0], [%1], 16;" :: "r"(dst_saddr), "l"(src) : "memory");
}
__device__ __forceinline__ void cp_commit() {
    asm volatile("cp.async.commit_group;" ::: "memory");
}
__device__ __forceinline__ void cp_wait0() {
    asm volatile("cp.async.wait_group 0;" ::: "memory");
}

// ---------------------------------------------------------------------------
// tf32 tensor-core GEMM:  C[m][n] = alpha * (sum_k A[m][k]*W[n][k] + bias[n])
// Block tile 128x128, K-step 16, 128 threads = 4 warps (2x2 grid of 64x64
// warp tiles). Double-buffered smem fed by cp.async (raw fp32); fragments
// loaded with ldmatrix.x4 and converted to tf32 (rna) in registers.
//
// SMEM layout per stage: A 128 rows x 16 words, then B 128 rows x 16 words.
// Swizzle: word col group kg (0..3) stored at kg ^ ((row>>1)&3). This makes
// both the 16B cp.async stores and the ldmatrix 8-lane phases hit all 32
// banks (verified: bank start = 16*(row&1) + 4*(kg^((row>>1)&3)) is a
// bijection over the 8 rows of a phase).
// Requires Md%128==0, Nd%128==0, Kd%16==0.
// ---------------------------------------------------------------------------
__device__ __forceinline__ void gemm_body(
    const float* __restrict__ A, const float* __restrict__ W,
    const float* __restrict__ bias, float* __restrict__ C,
    int Nd, int Kd, float alpha, int bm, int bn)
{
    __shared__ uint32_t sm[8192];   // 2 stages x (2048 A + 2048 B) words = 32KB

    const int tid  = threadIdx.x;
    const int lane = tid & 31;
    const int warp = tid >> 5;
    const int g    = lane >> 2;        // 0..7
    const int lq   = lane & 3;         // 0..3
    const int wm   = (warp >> 1) << 6; // 0,64
    const int wn   = (warp & 1) << 6;  // 0,64

    const uint32_t sbase = (uint32_t)__cvta_generic_to_shared(sm);

    // ---- store-side (cp.async destination) indices ----
    const int srow = tid >> 2;                       // 0..31 (+32*i)
    const int skg  = tid & 3;                        // 16B chunk within row
    const int ssw  = (skg ^ ((srow >> 1) & 3)) << 2; // swizzled word offset

    // ---- ldmatrix source addresses (stage 0; add stage byte offset) ----
    uint32_t aaddr[4][2], baddr[8];
    {
        const int ar  = (((lane >> 3) & 1) << 3) + (lane & 7); // row in 16-block
        const int at  = (lane >> 4) & 1;                        // k-subtile
        const int asw = (ar >> 1) & 3;
        #pragma unroll
        for (int rb = 0; rb < 4; rb++)
            #pragma unroll
            for (int kb = 0; kb < 2; kb++) {
                const int R = wm + rb * 16 + ar;
                aaddr[rb][kb] = sbase + (uint32_t)((R * 16 + (((kb * 2 + at) ^ asw) << 2)) * 4);
            }
        const int bn8 = lane & 7;
        const int bt  = (lane >> 3) & 3;
        const int bsw = (bn8 >> 1) & 3;
        #pragma unroll
        for (int cb = 0; cb < 8; cb++) {
            const int N = wn + cb * 8 + bn8;
            baddr[cb] = sbase + (uint32_t)(8192 + (N * 16 + ((bt ^ bsw) << 2)) * 4);
        }
    }

    const float* Agp = A + (size_t)(bm + srow) * Kd + (skg << 2);
    const float* Wgp = W + (size_t)(bn + srow) * Kd + (skg << 2);
    const size_t rstride = (size_t)Kd * 32;

    float acc[4][8][4];
    #pragma unroll
    for (int i = 0; i < 4; i++)
        #pragma unroll
        for (int j = 0; j < 8; j++)
            #pragma unroll
            for (int e = 0; e < 4; e++) acc[i][j][e] = 0.f;

    const int nslab = Kd >> 4;

    // Prologue: slab 0 -> stage 0
    {
        const uint32_t da = sbase + (uint32_t)((srow * 16 + ssw) * 4);
        const uint32_t db = da + 8192;
        #pragma unroll
        for (int i = 0; i < 4; i++) {
            cp_async16(da + i * 2048, Agp + i * rstride);   // 32 rows * 16 words * 4B
            cp_async16(db + i * 2048, Wgp + i * rstride);
        }
        cp_commit();
    }

    for (int s = 0; s < nslab; s++) {
        const uint32_t stb = (uint32_t)((s & 1) << 14);   // stage byte offset (16KB)

        cp_wait0();
        __syncthreads();   // slab s visible to all; prior readers of other stage done

        // Prefetch slab s+1 into the other stage (overlaps the MMAs below)
        if (s + 1 < nslab) {
            const uint32_t nstb = (uint32_t)(((s + 1) & 1) << 14);
            const uint32_t da = sbase + nstb + (uint32_t)((srow * 16 + ssw) * 4);
            const uint32_t db = da + 8192;
            const size_t ko = (size_t)(s + 1) << 4;
            #pragma unroll
            for (int i = 0; i < 4; i++) {
                cp_async16(da + i * 2048, Agp + i * rstride + ko);
                cp_async16(db + i * 2048, Wgp + i * rstride + ko);
            }
            cp_commit();
        }

        // B fragments for the whole slab (k 0..15), convert to tf32
        uint32_t bU[8][4];
        #pragma unroll
        for (int j = 0; j < 8; j++) {
            ldsm_x4(bU[j], baddr[j] + stb);
            #pragma unroll
            for (int e = 0; e < 4; e++) bU[j][e] = f2tf32(__uint_as_float(bU[j][e]));
        }

        #pragma unroll
        for (int kb = 0; kb < 2; kb++) {
            uint32_t aU[4][4];
            #pragma unroll
            for (int rb = 0; rb < 4; rb++) {
                ldsm_x4(aU[rb], aaddr[rb][kb] + stb);
                #pragma unroll
                for (int e = 0; e < 4; e++) aU[rb][e] = f2tf32(__uint_as_float(aU[rb][e]));
            }
            #pragma unroll
            for (int i = 0; i < 4; i++)
                #pragma unroll
                for (int j = 0; j < 8; j++)
                    mma_tf32(acc[i][j], aU[i], &bU[j][kb * 2]);
        }
    }

    // Epilogue: m16n8 accumulator layout -> C
    #pragma unroll
    for (int i = 0; i < 4; i++) {
        const int row = bm + wm + i * 16 + g;
        #pragma unroll
        for (int j = 0; j < 8; j++) {
            const int col = bn + wn + j * 8 + (lq << 1);
            const float b0 = bias[col], b1 = bias[col + 1];
            float* c0 = C + (size_t)row * Nd + col;
            float* c1 = C + (size_t)(row + 8) * Nd + col;
            c0[0] = alpha * (acc[i][j][0] + b0);
            c0[1] = alpha * (acc[i][j][1] + b1);
            c1[0] = alpha * (acc[i][j][2] + b0);
            c1[1] = alpha * (acc[i][j][3] + b1);
        }
    }
}

__global__ __launch_bounds__(128, 2) void gemm_qkv(
    const float* __restrict__ hidden,
    const float* __restrict__ Wq, const float* __restrict__ bq,
    const float* __restrict__ Wk, const float* __restrict__ bk,
    const float* __restrict__ Wv, const float* __restrict__ bv,
    float* __restrict__ q, float* __restrict__ k, float* __restrict__ v,
    float scaling)
{
    const float* W; const float* bias; float* C; float alpha;
    if (blockIdx.z == 0)      { W = Wq; bias = bq; C = q; alpha = scaling; }
    else if (blockIdx.z == 1) { W = Wk; bias = bk; C = k; alpha = 1.f; }
    else                      { W = Wv; bias = bv; C = v; alpha = 1.f; }
    gemm_body(hidden, W, bias, C, RK, EE, alpha, blockIdx.y * 128, blockIdx.x * 128);
}

__global__ __launch_bounds__(128, 2) void gemm_o(
    const float* __restrict__ att,
    const float* __restrict__ Wo, const float* __restrict__ bo,
    float* __restrict__ out)
{
    gemm_body(att, Wo, bo, out, EE, RK, 1.f, blockIdx.y * 128, blockIdx.x * 128);
}

// ---------------------------------------------------------------------------
// Tensor-core flash attention (unchanged from R14 passing version).
// ---------------------------------------------------------------------------
__global__ __launch_bounds__(128) void flash_attn_mma()
{
    __shared__ uint32_t Qs[64][36];
    __shared__ uint32_t Ks[64][36];
    __shared__ uint32_t Vs[64][36];
    __shared__ uint32_t Ps[64][68];

    const int b  = blockIdx.z;
    const int h  = blockIdx.y;
    const int qi = blockIdx.x;
    const int q0 = qi * 64;

    const int tid  = threadIdx.x;
    const int lane = tid & 31;
    const int warp = tid >> 5;
    const int g    = lane >> 2;   // 0..7
    const int lq   = lane & 3;    // 0..3
    const int wm   = warp << 4;   // 0,16,32,48

    for (int i = tid; i < 512; i += 128) {
        const int r = i >> 3, c = (i & 7) << 2;
        float4 f = *(const float4*)&g_q[((size_t)(b * SS + q0 + r)) * RK + h * DKQ + c];
        *(uint4*)&Qs[r][c] = make_uint4(f2tf32(f.x), f2tf32(f.y), f2tf32(f.z), f2tf32(f.w));
    }

    const int r0 = q0 + wm + g;
    float m0 = NEG_BIG, m1 = NEG_BIG;
    float l0 = 0.f, l1 = 0.f;
    float o[4][4];
    #pragma unroll
    for (int j = 0; j < 4; j++)
        #pragma unroll
        for (int e = 0; e < 4; e++) o[j][e] = 0.f;

    for (int t = 0; t <= qi; t++) {
        const int k0 = t * 64;
        __syncthreads();
        for (int i = tid; i < 512; i += 128) {
            const int r = i >> 3, c = (i & 7) << 2;
            const size_t gi = ((size_t)(b * SS + k0 + r)) * RK + h * DKQ + c;
            float4 fk = *(const float4*)&g_k[gi];
            float4 fv = *(const float4*)&g_v[gi];
            *(uint4*)&Ks[r][c] = make_uint4(f2tf32(fk.x), f2tf32(fk.y), f2tf32(fk.z), f2tf32(fk.w));
            *(uint4*)&Vs[r][c] = make_uint4(f2tf32(fv.x), f2tf32(fv.y), f2tf32(fv.z), f2tf32(fv.w));
        }
        __syncthreads();

        float s[8][4];
        #pragma unroll
        for (int j = 0; j < 8; j++)
            #pragma unroll
            for (int e = 0; e < 4; e++) s[j][e] = 0.f;

        #pragma unroll
        for (int ks = 0; ks < 32; ks += 8) {
            uint32_t af[4];
            af[0] = Qs[wm + g][ks + lq];
            af[1] = Qs[wm + 8 + g][ks + lq];
            af[2] = Qs[wm + g][ks + lq + 4];
            af[3] = Qs[wm + 8 + g][ks + lq + 4];
            #pragma unroll
            for (int j = 0; j < 8; j++) {
                uint32_t bf[2];
                bf[0] = Ks[j * 8 + g][ks + lq];
                bf[1] = Ks[j * 8 + g][ks + lq + 4];
                mma_tf32(s[j], af, bf);
            }
        }

        if (t == qi) {
            #pragma unroll
            for (int j = 0; j < 8; j++) {
                const int col = k0 + j * 8 + (lq << 1);
                if (col     > r0)     s[j][0] = NEG_BIG;
                if (col + 1 > r0)     s[j][1] = NEG_BIG;
                if (col     > r0 + 8) s[j][2] = NEG_BIG;
                if (col + 1 > r0 + 8) s[j][3] = NEG_BIG;
            }
        }

        float t0 = NEG_BIG, t1 = NEG_BIG;
        #pragma unroll
        for (int j = 0; j < 8; j++) {
            t0 = fmaxf(t0, fmaxf(s[j][0], s[j][1]));
            t1 = fmaxf(t1, fmaxf(s[j][2], s[j][3]));
        }
        t0 = fmaxf(t0, __shfl_xor_sync(0xffffffffu, t0, 1));
        t0 = fmaxf(t0, __shfl_xor_sync(0xffffffffu, t0, 2));
        t1 = fmaxf(t1, __shfl_xor_sync(0xffffffffu, t1, 1));
        t1 = fmaxf(t1, __shfl_xor_sync(0xffffffffu, t1, 2));

        const float mn0 = fmaxf(m0, t0);
        const float mn1 = fmaxf(m1, t1);
        const float sc0 = __expf(m0 - mn0);
        const float sc1 = __expf(m1 - mn1);

        float ls0 = 0.f, ls1 = 0.f;
        #pragma unroll
        for (int j = 0; j < 8; j++) {
            const float p00 = __expf(s[j][0] - mn0);
            const float p01 = __expf(s[j][1] - mn0);
            const float p10 = __expf(s[j][2] - mn1);
            const float p11 = __expf(s[j][3] - mn1);
            ls0 += p00 + p01;
            ls1 += p10 + p11;
            const int pc = j * 8 + (lq << 1);
            *(uint2*)&Ps[wm + g][pc]     = make_uint2(f2tf32(p00), f2tf32(p01));
            *(uint2*)&Ps[wm + 8 + g][pc] = make_uint2(f2tf32(p10), f2tf32(p11));
        }
        ls0 += __shfl_xor_sync(0xffffffffu, ls0, 1);
        ls0 += __shfl_xor_sync(0xffffffffu, ls0, 2);
        ls1 += __shfl_xor_sync(0xffffffffu, ls1, 1);
        ls1 += __shfl_xor_sync(0xffffffffu, ls1, 2);

        l0 = l0 * sc0 + ls0;
        l1 = l1 * sc1 + ls1;
        m0 = mn0;
        m1 = mn1;

        #pragma unroll
        for (int j = 0; j < 4; j++) {
            o[j][0] *= sc0; o[j][1] *= sc0;
            o[j][2] *= sc1; o[j][3] *= sc1;
        }

        __syncwarp();

        #pragma unroll
        for (int ks = 0; ks < 64; ks += 8) {
            uint32_t af[4];
            af[0] = Ps[wm + g][ks + lq];
            af[1] = Ps[wm + 8 + g][ks + lq];
            af[2] = Ps[wm + g][ks + lq + 4];
            af[3] = Ps[wm + 8 + g][ks + lq + 4];
            #pragma unroll
            for (int j = 0; j < 4; j++) {
                uint32_t bf[2];
                bf[0] = Vs[ks + lq][j * 8 + g];
                bf[1] = Vs[ks + lq + 4][j * 8 + g];
                mma_tf32(o[j], af, bf);
            }
        }
    }

    const float inv0 = 1.f / l0;
    const float inv1 = 1.f / l1;
    const size_t base0 = ((size_t)(b * SS + r0))     * RK + h * DVV;
    const size_t base1 = ((size_t)(b * SS + r0 + 8)) * RK + h * DVV;
    #pragma unroll
    for (int j = 0; j < 4; j++) {
        const int col = j * 8 + (lq << 1);
        g_att[base0 + col]     = o[j][0] * inv0;
        g_att[base0 + col + 1] = o[j][1] * inv0;
        g_att[base1 + col]     = o[j][2] * inv1;
        g_att[base1 + col + 1] = o[j][3] * inv1;
    }
}

// ---------------------------------------------------------------------------
extern "C" void kernel_launch(void* const* d_in, const int* in_sizes, int n_in,
                              void* d_out, int out_size)
{
    const float* hidden = (const float*)d_in[0];
    const float* Wq     = (const float*)d_in[2];
    const float* bq     = (const float*)d_in[3];
    const float* Wk     = (const float*)d_in[4];
    const float* bk     = (const float*)d_in[5];
    const float* Wv     = (const float*)d_in[6];
    const float* bv     = (const float*)d_in[7];
    const float* Wo     = (const float*)d_in[8];
    const float* bo     = (const float*)d_in[9];
    float* out = (float*)d_out;

    float* q = nullptr; float* k = nullptr; float* v = nullptr; float* att = nullptr;
    cudaGetSymbolAddress((void**)&q,   g_q);
    cudaGetSymbolAddress((void**)&k,   g_k);
    cudaGetSymbolAddress((void**)&v,   g_v);
    cudaGetSymbolAddress((void**)&att, g_att);

    const float scaling = 0.125f;  // 64^-0.5 (original head dim)

    // Fused projections: (4096 x 2048) @ (1024 x 2048)^T -> 3x (4096 x 1024)
    {
        dim3 grid(RK / 128, MM / 128, 3);
        gemm_qkv<<<grid, 128>>>(hidden, Wq, bq, Wk, bk, Wv, bv, q, k, v, scaling);
    }

    // Attention (tensor-core flash; analytic causal mask)
    {
        dim3 grid(SS / 64, HH, BB);
        flash_attn_mma<<<grid, 128>>>();
    }

    // Output projection: (4096 x 1024) @ (2048 x 1024)^T -> (4096 x 2048)
    {
        dim3 grid(EE / 128, MM / 128);
        gemm_o<<<grid, 128>>>(att, Wo, bo, out);
    }
}

// round 16
// speedup vs baseline: 4.1071x; 1.1265x over previous
#include <cuda_runtime.h>
#include <math.h>
#include <stdint.h>

// Problem constants
#define BB   2
#define SS   2048
#define EE   2048
#define HH   32
#define DKQ  32
#define DVV  32
#define RK   1024
#define MM   (BB*SS)   // 4096

#define NEG_BIG (-1e30f)

// Scratch (no cudaMalloc allowed). All tf32-bit payloads stored as float.
__device__ float g_q[MM * RK];
__device__ float g_k[MM * RK];
__device__ float g_v[MM * RK];
__device__ float g_att[MM * RK];
__device__ float g_hid[MM * EE];          // hidden, tf32-rounded
__device__ float g_w[4 * RK * EE];        // Wq | Wk | Wv | Wo, tf32-rounded

// ---------------------------------------------------------------------------
// tf32 / mma / ldmatrix / cp.async helpers
// ---------------------------------------------------------------------------
__device__ __forceinline__ uint32_t f2tf32(float x) {
    uint32_t r;
    asm("cvt.rna.tf32.f32 %0, %1;" : "=r"(r) : "f"(x));
    return r;
}
__device__ __forceinline__ float f2tf32f(float x) {
    return __uint_as_float(f2tf32(x));
}

__device__ __forceinline__ void mma_tf32(float* c, const uint32_t* a, const uint32_t* b) {
    asm volatile(
        "mma.sync.aligned.m16n8k8.row.col.f32.tf32.tf32.f32 "
        "{%0,%1,%2,%3}, {%4,%5,%6,%7}, {%8,%9}, {%0,%1,%2,%3};"
        : "+f"(c[0]), "+f"(c[1]), "+f"(c[2]), "+f"(c[3])
        : "r"(a[0]), "r"(a[1]), "r"(a[2]), "r"(a[3]),
          "r"(b[0]), "r"(b[1]));
}

__device__ __forceinline__ void ldsm_x4(uint32_t* r, uint32_t saddr) {
    asm volatile(
        "ldmatrix.sync.aligned.m8n8.x4.shared.b16 {%0,%1,%2,%3}, [%4];"
        : "=r"(r[0]), "=r"(r[1]), "=r"(r[2]), "=r"(r[3]) : "r"(saddr));
}

__device__ __forceinline__ void cp_async16(uint32_t dst_saddr, const void* src) {
    asm volatile("cp.async.cg.shared.global [%0], [%1], 16;" :: "r"(dst_saddr), "l"(src) : "memory");
}
__device__ __forceinline__ void cp_commit() {
    asm volatile("cp.async.commit_group;" ::: "memory");
}
__device__ __forceinline__ void cp_wait0() {
    asm volatile("cp.async.wait_group 0;" ::: "memory");
}

// ---------------------------------------------------------------------------
// Elementwise tf32 rounding: dst[i] = tf32(src[i]). n must be /4.
// ---------------------------------------------------------------------------
__global__ __launch_bounds__(256) void cvt_tf32_kernel(
    const float4* __restrict__ src, float4* __restrict__ dst, int n4)
{
    int i = blockIdx.x * blockDim.x + threadIdx.x;
    if (i < n4) {
        float4 f = src[i];
        dst[i] = make_float4(f2tf32f(f.x), f2tf32f(f.y), f2tf32f(f.z), f2tf32f(f.w));
    }
}

// ---------------------------------------------------------------------------
// tf32 tensor-core GEMM:  C[m][n] = alpha * (sum_k A[m][k]*W[n][k] + bias[n])
// Inputs A and W must already be tf32-rounded bit patterns: the inner loop
// feeds ldmatrix results straight into mma (no cvt on the critical path).
// Block tile 128x128, K-step 16, 128 threads = 4 warps (2x2 of 64x64).
// Double-buffered cp.async; swizzle as in R15 (verified conflict-free).
// OUT_TF32: epilogue additionally rounds the result to tf32 (for q/k/v).
// ---------------------------------------------------------------------------
template <bool OUT_TF32>
__device__ __forceinline__ void gemm_body(
    const float* __restrict__ A, const float* __restrict__ W,
    const float* __restrict__ bias, float* __restrict__ C,
    int Nd, int Kd, float alpha, int bm, int bn)
{
    __shared__ uint32_t sm[8192];   // 2 stages x (2048 A + 2048 B) words = 32KB

    const int tid  = threadIdx.x;
    const int lane = tid & 31;
    const int warp = tid >> 5;
    const int g    = lane >> 2;        // 0..7
    const int lq   = lane & 3;         // 0..3
    const int wm   = (warp >> 1) << 6; // 0,64
    const int wn   = (warp & 1) << 6;  // 0,64

    const uint32_t sbase = (uint32_t)__cvta_generic_to_shared(sm);

    const int srow = tid >> 2;
    const int skg  = tid & 3;
    const int ssw  = (skg ^ ((srow >> 1) & 3)) << 2;

    uint32_t aaddr[4][2], baddr[8];
    {
        const int ar  = (((lane >> 3) & 1) << 3) + (lane & 7);
        const int at  = (lane >> 4) & 1;
        const int asw = (ar >> 1) & 3;
        #pragma unroll
        for (int rb = 0; rb < 4; rb++)
            #pragma unroll
            for (int kb = 0; kb < 2; kb++) {
                const int R = wm + rb * 16 + ar;
                aaddr[rb][kb] = sbase + (uint32_t)((R * 16 + (((kb * 2 + at) ^ asw) << 2)) * 4);
            }
        const int bn8 = lane & 7;
        const int bt  = (lane >> 3) & 3;
        const int bsw = (bn8 >> 1) & 3;
        #pragma unroll
        for (int cb = 0; cb < 8; cb++) {
            const int N = wn + cb * 8 + bn8;
            baddr[cb] = sbase + (uint32_t)(8192 + (N * 16 + ((bt ^ bsw) << 2)) * 4);
        }
    }

    const float* Agp = A + (size_t)(bm + srow) * Kd + (skg << 2);
    const float* Wgp = W + (size_t)(bn + srow) * Kd + (skg << 2);
    const size_t rstride = (size_t)Kd * 32;

    float acc[4][8][4];
    #pragma unroll
    for (int i = 0; i < 4; i++)
        #pragma unroll
        for (int j = 0; j < 8; j++)
            #pragma unroll
            for (int e = 0; e < 4; e++) acc[i][j][e] = 0.f;

    const int nslab = Kd >> 4;

    {
        const uint32_t da = sbase + (uint32_t)((srow * 16 + ssw) * 4);
        const uint32_t db = da + 8192;
        #pragma unroll
        for (int i = 0; i < 4; i++) {
            cp_async16(da + i * 2048, Agp + i * rstride);
            cp_async16(db + i * 2048, Wgp + i * rstride);
        }
        cp_commit();
    }

    for (int s = 0; s < nslab; s++) {
        const uint32_t stb = (uint32_t)((s & 1) << 14);

        cp_wait0();
        __syncthreads();

        if (s + 1 < nslab) {
            const uint32_t nstb = (uint32_t)(((s + 1) & 1) << 14);
            const uint32_t da = sbase + nstb + (uint32_t)((srow * 16 + ssw) * 4);
            const uint32_t db = da + 8192;
            const size_t ko = (size_t)(s + 1) << 4;
            #pragma unroll
            for (int i = 0; i < 4; i++) {
                cp_async16(da + i * 2048, Agp + i * rstride + ko);
                cp_async16(db + i * 2048, Wgp + i * rstride + ko);
            }
            cp_commit();
        }

        // Fragments: pure ldsm -> mma (operands pre-rounded to tf32)
        uint32_t bU[8][4];
        #pragma unroll
        for (int j = 0; j < 8; j++)
            ldsm_x4(bU[j], baddr[j] + stb);

        #pragma unroll
        for (int kb = 0; kb < 2; kb++) {
            uint32_t aU[4][4];
            #pragma unroll
            for (int rb = 0; rb < 4; rb++)
                ldsm_x4(aU[rb], aaddr[rb][kb] + stb);
            #pragma unroll
            for (int i = 0; i < 4; i++)
                #pragma unroll
                for (int j = 0; j < 8; j++)
                    mma_tf32(acc[i][j], aU[i], &bU[j][kb * 2]);
        }
    }

    #pragma unroll
    for (int i = 0; i < 4; i++) {
        const int row = bm + wm + i * 16 + g;
        #pragma unroll
        for (int j = 0; j < 8; j++) {
            const int col = bn + wn + j * 8 + (lq << 1);
            const float b0 = bias[col], b1 = bias[col + 1];
            float v00 = alpha * (acc[i][j][0] + b0);
            float v01 = alpha * (acc[i][j][1] + b1);
            float v10 = alpha * (acc[i][j][2] + b0);
            float v11 = alpha * (acc[i][j][3] + b1);
            if (OUT_TF32) {
                v00 = f2tf32f(v00); v01 = f2tf32f(v01);
                v10 = f2tf32f(v10); v11 = f2tf32f(v11);
            }
            float* c0 = C + (size_t)row * Nd + col;
            float* c1 = C + (size_t)(row + 8) * Nd + col;
            c0[0] = v00; c0[1] = v01;
            c1[0] = v10; c1[1] = v11;
        }
    }
}

__global__ __launch_bounds__(128, 2) void gemm_qkv(
    const float* __restrict__ bq, const float* __restrict__ bk,
    const float* __restrict__ bv,
    float* __restrict__ q, float* __restrict__ k, float* __restrict__ v,
    float scaling)
{
    const float* W; const float* bias; float* C; float alpha;
    if (blockIdx.z == 0)      { W = g_w;               bias = bq; C = q; alpha = scaling; }
    else if (blockIdx.z == 1) { W = g_w + RK * EE;     bias = bk; C = k; alpha = 1.f; }
    else                      { W = g_w + 2 * RK * EE; bias = bv; C = v; alpha = 1.f; }
    gemm_body<true>(g_hid, W, bias, C, RK, EE, alpha, blockIdx.y * 128, blockIdx.x * 128);
}

__global__ __launch_bounds__(128, 2) void gemm_o(
    const float* __restrict__ bo, float* __restrict__ out)
{
    gemm_body<false>(g_att, g_w + 3 * RK * EE, bo, out, EE, RK, 1.f,
                     blockIdx.y * 128, blockIdx.x * 128);
}

// ---------------------------------------------------------------------------
// Tensor-core flash attention. q/k/v already hold tf32 bit patterns, so the
// smem tile loads are plain copies (no cvt). P still converts post-exp.
// Epilogue rounds the output to tf32 for gemm_o's consumption.
// ---------------------------------------------------------------------------
__global__ __launch_bounds__(128) void flash_attn_mma()
{
    __shared__ uint32_t Qs[64][36];
    __shared__ uint32_t Ks[64][36];
    __shared__ uint32_t Vs[64][36];
    __shared__ uint32_t Ps[64][68];

    const int b  = blockIdx.z;
    const int h  = blockIdx.y;
    const int qi = blockIdx.x;
    const int q0 = qi * 64;

    const int tid  = threadIdx.x;
    const int lane = tid & 31;
    const int warp = tid >> 5;
    const int g    = lane >> 2;   // 0..7
    const int lq   = lane & 3;    // 0..3
    const int wm   = warp << 4;   // 0,16,32,48

    for (int i = tid; i < 512; i += 128) {
        const int r = i >> 3, c = (i & 7) << 2;
        *(uint4*)&Qs[r][c] =
            *(const uint4*)&g_q[((size_t)(b * SS + q0 + r)) * RK + h * DKQ + c];
    }

    const int r0 = q0 + wm + g;
    float m0 = NEG_BIG, m1 = NEG_BIG;
    float l0 = 0.f, l1 = 0.f;
    float o[4][4];
    #pragma unroll
    for (int j = 0; j < 4; j++)
        #pragma unroll
        for (int e = 0; e < 4; e++) o[j][e] = 0.f;

    for (int t = 0; t <= qi; t++) {
        const int k0 = t * 64;
        __syncthreads();
        for (int i = tid; i < 512; i += 128) {
            const int r = i >> 3, c = (i & 7) << 2;
            const size_t gi = ((size_t)(b * SS + k0 + r)) * RK + h * DKQ + c;
            *(uint4*)&Ks[r][c] = *(const uint4*)&g_k[gi];
            *(uint4*)&Vs[r][c] = *(const uint4*)&g_v[gi];
        }
        __syncthreads();

        float s[8][4];
        #pragma unroll
        for (int j = 0; j < 8; j++)
            #pragma unroll
            for (int e = 0; e < 4; e++) s[j][e] = 0.f;

        #pragma unroll
        for (int ks = 0; ks < 32; ks += 8) {
            uint32_t af[4];
            af[0] = Qs[wm + g][ks + lq];
            af[1] = Qs[wm + 8 + g][ks + lq];
            af[2] = Qs[wm + g][ks + lq + 4];
            af[3] = Qs[wm + 8 + g][ks + lq + 4];
            #pragma unroll
            for (int j = 0; j < 8; j++) {
                uint32_t bf[2];
                bf[0] = Ks[j * 8 + g][ks + lq];
                bf[1] = Ks[j * 8 + g][ks + lq + 4];
                mma_tf32(s[j], af, bf);
            }
        }

        if (t == qi) {
            #pragma unroll
            for (int j = 0; j < 8; j++) {
                const int col = k0 + j * 8 + (lq << 1);
                if (col     > r0)     s[j][0] = NEG_BIG;
                if (col + 1 > r0)     s[j][1] = NEG_BIG;
                if (col     > r0 + 8) s[j][2] = NEG_BIG;
                if (col + 1 > r0 + 8) s[j][3] = NEG_BIG;
            }
        }

        float t0 = NEG_BIG, t1 = NEG_BIG;
        #pragma unroll
        for (int j = 0; j < 8; j++) {
            t0 = fmaxf(t0, fmaxf(s[j][0], s[j][1]));
            t1 = fmaxf(t1, fmaxf(s[j][2], s[j][3]));
        }
        t0 = fmaxf(t0, __shfl_xor_sync(0xffffffffu, t0, 1));
        t0 = fmaxf(t0, __shfl_xor_sync(0xffffffffu, t0, 2));
        t1 = fmaxf(t1, __shfl_xor_sync(0xffffffffu, t1, 1));
        t1 = fmaxf(t1, __shfl_xor_sync(0xffffffffu, t1, 2));

        const float mn0 = fmaxf(m0, t0);
        const float mn1 = fmaxf(m1, t1);
        const float sc0 = __expf(m0 - mn0);
        const float sc1 = __expf(m1 - mn1);

        float ls0 = 0.f, ls1 = 0.f;
        #pragma unroll
        for (int j = 0; j < 8; j++) {
            const float p00 = __expf(s[j][0] - mn0);
            const float p01 = __expf(s[j][1] - mn0);
            const float p10 = __expf(s[j][2] - mn1);
            const float p11 = __expf(s[j][3] - mn1);
            ls0 += p00 + p01;
            ls1 += p10 + p11;
            const int pc = j * 8 + (lq << 1);
            *(uint2*)&Ps[wm + g][pc]     = make_uint2(f2tf32(p00), f2tf32(p01));
            *(uint2*)&Ps[wm + 8 + g][pc] = make_uint2(f2tf32(p10), f2tf32(p11));
        }
        ls0 += __shfl_xor_sync(0xffffffffu, ls0, 1);
        ls0 += __shfl_xor_sync(0xffffffffu, ls0, 2);
        ls1 += __shfl_xor_sync(0xffffffffu, ls1, 1);
        ls1 += __shfl_xor_sync(0xffffffffu, ls1, 2);

        l0 = l0 * sc0 + ls0;
        l1 = l1 * sc1 + ls1;
        m0 = mn0;
        m1 = mn1;

        #pragma unroll
        for (int j = 0; j < 4; j++) {
            o[j][0] *= sc0; o[j][1] *= sc0;
            o[j][2] *= sc1; o[j][3] *= sc1;
        }

        __syncwarp();

        #pragma unroll
        for (int ks = 0; ks < 64; ks += 8) {
            uint32_t af[4];
            af[0] = Ps[wm + g][ks + lq];
            af[1] = Ps[wm + 8 + g][ks + lq];
            af[2] = Ps[wm + g][ks + lq + 4];
            af[3] = Ps[wm + 8 + g][ks + lq + 4];
            #pragma unroll
            for (int j = 0; j < 4; j++) {
                uint32_t bf[2];
                bf[0] = Vs[ks + lq][j * 8 + g];
                bf[1] = Vs[ks + lq + 4][j * 8 + g];
                mma_tf32(o[j], af, bf);
            }
        }
    }

    const float inv0 = 1.f / l0;
    const float inv1 = 1.f / l1;
    const size_t base0 = ((size_t)(b * SS + r0))     * RK + h * DVV;
    const size_t base1 = ((size_t)(b * SS + r0 + 8)) * RK + h * DVV;
    #pragma unroll
    for (int j = 0; j < 4; j++) {
        const int col = j * 8 + (lq << 1);
        g_att[base0 + col]     = f2tf32f(o[j][0] * inv0);
        g_att[base0 + col + 1] = f2tf32f(o[j][1] * inv0);
        g_att[base1 + col]     = f2tf32f(o[j][2] * inv1);
        g_att[base1 + col + 1] = f2tf32f(o[j][3] * inv1);
    }
}

// ---------------------------------------------------------------------------
extern "C" void kernel_launch(void* const* d_in, const int* in_sizes, int n_in,
                              void* d_out, int out_size)
{
    const float* hidden = (const float*)d_in[0];
    const float* Wq     = (const float*)d_in[2];
    const float* bq     = (const float*)d_in[3];
    const float* Wk     = (const float*)d_in[4];
    const float* bk     = (const float*)d_in[5];
    const float* Wv     = (const float*)d_in[6];
    const float* bv     = (const float*)d_in[7];
    const float* Wo     = (const float*)d_in[8];
    const float* bo     = (const float*)d_in[9];
    float* out = (float*)d_out;

    float* q = nullptr; float* k = nullptr; float* v = nullptr;
    float* hid = nullptr; float* w = nullptr;
    cudaGetSymbolAddress((void**)&q,   g_q);
    cudaGetSymbolAddress((void**)&k,   g_k);
    cudaGetSymbolAddress((void**)&v,   g_v);
    cudaGetSymbolAddress((void**)&hid, g_hid);
    cudaGetSymbolAddress((void**)&w,   g_w);

    const float scaling = 0.125f;  // 64^-0.5 (original head dim)

    // Pre-round operands to tf32 (idempotent, deterministic).
    {
        const int n4h = (MM * EE) / 4;       // hidden: 8M elems
        const int n4w = (RK * EE) / 4;       // each W: 2M elems
        cvt_tf32_kernel<<<(n4h + 255) / 256, 256>>>((const float4*)hidden, (float4*)hid, n4h);
        cvt_tf32_kernel<<<(n4w + 255) / 256, 256>>>((const float4*)Wq, (float4*)(w),               n4w);
        cvt_tf32_kernel<<<(n4w + 255) / 256, 256>>>((const float4*)Wk, (float4*)(w + RK * EE),     n4w);
        cvt_tf32_kernel<<<(n4w + 255) / 256, 256>>>((const float4*)Wv, (float4*)(w + 2 * RK * EE), n4w);
        cvt_tf32_kernel<<<(n4w + 255) / 256, 256>>>((const float4*)Wo, (float4*)(w + 3 * RK * EE), n4w);
    }

    // Fused projections: (4096 x 2048) @ (1024 x 2048)^T -> 3x (4096 x 1024)
    {
        dim3 grid(RK / 128, MM / 128, 3);
        gemm_qkv<<<grid, 128>>>(bq, bk, bv, q, k, v, scaling);
    }

    // Attention (tensor-core flash; analytic causal mask)
    {
        dim3 grid(SS / 64, HH, BB);
        flash_attn_mma<<<grid, 128>>>();
    }

    // Output projection: (4096 x 1024) @ (2048 x 1024)^T -> (4096 x 2048)
    {
        dim3 grid(EE / 128, MM / 128);
        gemm_o<<<grid, 128>>>(bo, out);
    }
}